// round 14
// baseline (speedup 1.0000x reference)
#include <cuda_runtime.h>
#include <cuda_fp16.h>
#include <cstdint>

#define BQ 8192
#define DD 512
#define PK 4096
#define CC 1000
#define NPAD 1024
#define EPS_F 1e-3f
#define NT1 (PK / 128)   // 32 partials per row

// ---------------- scratch ----------------
__device__ __align__(16) __half g_Wh[(size_t)BQ * PK];
__device__ __align__(16) __half g_Vth[(size_t)NPAD * PK];
__device__ float g_part[(size_t)BQ * NT1];
__device__ float g_inv_rowsum[BQ];
__device__ float g_xn2[BQ];
__device__ float g_kn2[PK];

// ---------------- helpers ----------------
__device__ __forceinline__ uint32_t smem_u32(const void* p) {
    uint32_t a;
    asm("{ .reg .u64 t; cvta.to.shared.u64 t, %1; cvt.u32.u64 %0, t; }" : "=r"(a) : "l"(p));
    return a;
}

__device__ __forceinline__ uint32_t pack_h2(float a, float b) {
    __half2 h = __floats2half2_rn(a, b);
    return *reinterpret_cast<uint32_t*>(&h);
}

__device__ __forceinline__ void mma_f16(float* c, const uint32_t* a, const uint32_t* b) {
    asm volatile(
        "mma.sync.aligned.m16n8k16.row.col.f32.f16.f16.f32 "
        "{%0,%1,%2,%3},{%4,%5,%6,%7},{%8,%9},{%0,%1,%2,%3};"
        : "+f"(c[0]), "+f"(c[1]), "+f"(c[2]), "+f"(c[3])
        : "r"(a[0]), "r"(a[1]), "r"(a[2]), "r"(a[3]), "r"(b[0]), "r"(b[1]));
}

__device__ __forceinline__ void ldsm_x4(uint32_t* r, uint32_t addr) {
    asm volatile("ldmatrix.sync.aligned.m8n8.x4.shared.b16 {%0,%1,%2,%3}, [%4];"
        : "=r"(r[0]), "=r"(r[1]), "=r"(r[2]), "=r"(r[3]) : "r"(addr));
}

#define CP_ASYNC16(dst, src) \
    asm volatile("cp.async.cg.shared.global [%0], [%1], 16;" :: "r"(dst), "l"(src) : "memory")
#define CP_COMMIT()  asm volatile("cp.async.commit_group;" ::: "memory")
#define CP_WAIT2()   asm volatile("cp.async.wait_group 2;" ::: "memory")

// GEMM1 smem: 128 rows x 32B; byte(r,c) = r*32 + ((c ^ ((r>>2)&1))<<4)
#define ROWB1  32
#define BUFB1  4096
// GEMM2 smem: 128 rows x 64B; byte(r,c) = r*64 + ((c ^ ((r>>1)&3))<<4)
#define ROWB2  64
#define BUFB2  8192
#define SMEM2_SZ (8 * BUFB2)   // 4 stages x (A+B) = 65536

// ---------------- small kernels ----------------
// Merged norms: blocks [0, BQ) -> X rows, [BQ, BQ+PK) -> K rows
__global__ void row_norm2_all(const float* __restrict__ X, const float* __restrict__ K) {
    int b = blockIdx.x;
    const float* src;
    int row;
    if (b < BQ) { src = X + (size_t)b * DD; row = b; }
    else        { src = K + (size_t)(b - BQ) * DD; row = b - BQ; }
    float s = 0.f;
    for (int i = threadIdx.x; i < DD; i += blockDim.x) { float v = src[i]; s = fmaf(v, v, s); }
    #pragma unroll
    for (int o = 16; o > 0; o >>= 1) s += __shfl_xor_sync(0xffffffffu, s, o);
    __shared__ float red[4];
    if ((threadIdx.x & 31) == 0) red[threadIdx.x >> 5] = s;
    __syncthreads();
    if (threadIdx.x == 0) {
        float t = red[0] + red[1] + red[2] + red[3];
        if (b < BQ) g_xn2[row] = t; else g_kn2[row] = t;
    }
}

__global__ void transpose_vh_kernel(const float* __restrict__ V) {
    __shared__ float t[32][33];
    int nb = blockIdx.x * 32, kb = blockIdx.y * 32;
    int tx = threadIdx.x, ty = threadIdx.y;
    #pragma unroll
    for (int i = 0; i < 32; i += 8) {
        float v = 0.f;
        if (nb + tx < CC) v = V[(size_t)(kb + ty + i) * CC + nb + tx];
        t[ty + i][tx] = v;
    }
    __syncthreads();
    #pragma unroll
    for (int i = 0; i < 32; i += 8)
        g_Vth[(size_t)(nb + ty + i) * PK + kb + tx] = __float2half_rn(t[tx][ty + i]);
}

__global__ void reduce_rowsum_kernel() {
    int r = blockIdx.x * blockDim.x + threadIdx.x;
    if (r < BQ) {
        const float4* p = reinterpret_cast<const float4*>(&g_part[(size_t)r * NT1]);
        float s = 0.f;
        #pragma unroll
        for (int i = 0; i < NT1 / 4; i++) {
            float4 v = p[i];
            s += (v.x + v.y) + (v.z + v.w);
        }
        g_inv_rowsum[r] = 1.f / s;
    }
}

// ============================ GEMM1 (R13 verbatim) ============================
struct FragOffsets1 {
    uint32_t a[4];
    uint32_t b[2];
};

__device__ __forceinline__ FragOffsets1 make_frag_offsets1(int lane, int wm, int wn) {
    FragOffsets1 fo;
    {
        int r0 = wm * 64 + (lane & 7) + ((lane >> 3) & 1) * 8;
        int c  = (lane >> 4) & 1;
        int sw = (r0 >> 2) & 1;
        #pragma unroll
        for (int mt = 0; mt < 4; mt++)
            fo.a[mt] = (uint32_t)(r0 + mt * 16) * ROWB1 + (uint32_t)((c ^ sw) << 4);
    }
    {
        int g = lane >> 3;
        int c = g & 1;
        #pragma unroll
        for (int p = 0; p < 2; p++) {
            int r = wn * 32 + (2 * p + (g >> 1)) * 8 + (lane & 7);
            fo.b[p] = (uint32_t)r * ROWB1 + (uint32_t)((c ^ ((r >> 2) & 1)) << 4);
        }
    }
    return fo;
}

__device__ __forceinline__ void compute_tile1(uint32_t aB, uint32_t bB,
                                              const FragOffsets1& fo, float c[4][4][4]) {
    uint32_t af[4][4], bq[2][4];
    #pragma unroll
    for (int mt = 0; mt < 4; mt++) ldsm_x4(af[mt], aB + fo.a[mt]);
    #pragma unroll
    for (int p = 0; p < 2; p++)   ldsm_x4(bq[p], bB + fo.b[p]);
    #pragma unroll
    for (int mt = 0; mt < 4; mt++)
        #pragma unroll
        for (int nt = 0; nt < 4; nt++)
            mma_f16(c[mt][nt], af[mt], &bq[nt >> 1][(nt & 1) * 2]);
}

__global__ void __launch_bounds__(256) gemm1_h(const float* __restrict__ X,
                                               const float* __restrict__ Km) {
    __shared__ __align__(16) uint8_t As[2][BUFB1];
    __shared__ __align__(16) uint8_t Bs[2][BUFB1];
    __shared__ float rs[128 * 4];

    const int tid  = threadIdx.x;
    const int lane = tid & 31;
    const int wid  = tid >> 5;
    const int wm   = wid >> 2, wn = wid & 3;
    const int fr = lane >> 2, fc = lane & 3;
    const int bm = blockIdx.y * 128, bn = blockIdx.x * 128;

    const int lm  = tid >> 2;
    const int lk4 = (tid & 3) * 4;
    const int ch  = (tid & 3) >> 1;
    const int h8  = tid & 1;
    const int sw  = (lm >> 2) & 1;
    const uint32_t soA0 = (uint32_t)lm * ROWB1        + (uint32_t)((ch ^ sw) << 4) + h8 * 8;
    const uint32_t soA1 = (uint32_t)(lm + 64) * ROWB1 + (uint32_t)((ch ^ sw) << 4) + h8 * 8;

    const float* pA0 = X  + (size_t)(bm + lm) * DD + lk4;
    const float* pA1 = pA0 + (size_t)64 * DD;
    const float* pB0 = Km + (size_t)(bn + lm) * DD + lk4;
    const float* pB1 = pB0 + (size_t)64 * DD;

    float4 ra0 = *reinterpret_cast<const float4*>(pA0);
    float4 ra1 = *reinterpret_cast<const float4*>(pA1);
    float4 rb0 = *reinterpret_cast<const float4*>(pB0);
    float4 rb1 = *reinterpret_cast<const float4*>(pB1);

    float c[4][4][4];
    #pragma unroll
    for (int i = 0; i < 4; i++)
        #pragma unroll
        for (int j = 0; j < 4; j++)
            #pragma unroll
            for (int r = 0; r < 4; r++) c[i][j][r] = 0.f;

    const FragOffsets1 fo = make_frag_offsets1(lane, wm, wn);
    const uint32_t sbA = smem_u32(&As[0][0]);
    const uint32_t sbB = smem_u32(&Bs[0][0]);

    const int T = DD / 16;      // 32
    #pragma unroll 1
    for (int t = 0; t < T; t++) {
        int buf = t & 1;
        {
            uint2 u;
            u.x = pack_h2(ra0.x, ra0.y); u.y = pack_h2(ra0.z, ra0.w);
            *reinterpret_cast<uint2*>(&As[buf][soA0]) = u;
            u.x = pack_h2(ra1.x, ra1.y); u.y = pack_h2(ra1.z, ra1.w);
            *reinterpret_cast<uint2*>(&As[buf][soA1]) = u;
            u.x = pack_h2(rb0.x, rb0.y); u.y = pack_h2(rb0.z, rb0.w);
            *reinterpret_cast<uint2*>(&Bs[buf][soA0]) = u;
            u.x = pack_h2(rb1.x, rb1.y); u.y = pack_h2(rb1.z, rb1.w);
            *reinterpret_cast<uint2*>(&Bs[buf][soA1]) = u;
        }
        __syncthreads();
        if (t + 1 < T) {
            int off = (t + 1) * 16;
            ra0 = *reinterpret_cast<const float4*>(pA0 + off);
            ra1 = *reinterpret_cast<const float4*>(pA1 + off);
            rb0 = *reinterpret_cast<const float4*>(pB0 + off);
            rb1 = *reinterpret_cast<const float4*>(pB1 + off);
        }
        compute_tile1(sbA + buf * BUFB1, sbB + buf * BUFB1, fo, c);
    }

    // Epilogue: W -> g_Wh (half) + fused row-sum partials
    float rsum[4][2];
    #pragma unroll
    for (int mt = 0; mt < 4; mt++) { rsum[mt][0] = 0.f; rsum[mt][1] = 0.f; }

    #pragma unroll
    for (int mt = 0; mt < 4; mt++) {
        int row0 = bm + wm * 64 + mt * 16 + fr;
        float xn0 = g_xn2[row0];
        float xn1 = g_xn2[row0 + 8];
        #pragma unroll
        for (int nt = 0; nt < 4; nt++) {
            int col = bn + wn * 32 + nt * 8 + 2 * fc;
            float kn0 = g_kn2[col], kn1 = g_kn2[col + 1];
            float w00 = 1.f / (EPS_F + fmaxf(fmaf(-2.f, c[mt][nt][0], xn0 + kn0), 0.f));
            float w01 = 1.f / (EPS_F + fmaxf(fmaf(-2.f, c[mt][nt][1], xn0 + kn1), 0.f));
            float w10 = 1.f / (EPS_F + fmaxf(fmaf(-2.f, c[mt][nt][2], xn1 + kn0), 0.f));
            float w11 = 1.f / (EPS_F + fmaxf(fmaf(-2.f, c[mt][nt][3], xn1 + kn1), 0.f));
            __half2 h0 = __floats2half2_rn(w00, w01);
            __half2 h1 = __floats2half2_rn(w10, w11);
            float2 f0 = __half22float2(h0), f1 = __half22float2(h1);
            rsum[mt][0] += f0.x + f0.y;
            rsum[mt][1] += f1.x + f1.y;
            *reinterpret_cast<__half2*>(&g_Wh[(size_t)row0 * PK + col])       = h0;
            *reinterpret_cast<__half2*>(&g_Wh[(size_t)(row0 + 8) * PK + col]) = h1;
        }
    }

    __syncthreads();
    #pragma unroll
    for (int mt = 0; mt < 4; mt++) {
        #pragma unroll
        for (int rh = 0; rh < 2; rh++) {
            float v = rsum[mt][rh];
            v += __shfl_xor_sync(0xffffffffu, v, 1);
            v += __shfl_xor_sync(0xffffffffu, v, 2);
            if (fc == 0) {
                int rl = wm * 64 + mt * 16 + fr + rh * 8;
                rs[rl * 4 + wn] = v;
            }
        }
    }
    __syncthreads();
    if (tid < 128) {
        float s = rs[tid * 4] + rs[tid * 4 + 1] + rs[tid * 4 + 2] + rs[tid * 4 + 3];
        g_part[(size_t)(bm + tid) * NT1 + blockIdx.x] = s;
    }
}

// ============================ GEMM2 (4-stage cp.async ring, 64KB dynamic) ============================
struct FragOffsets2 {
    uint32_t a[4];
    uint32_t b[2];
};

__device__ __forceinline__ FragOffsets2 make_frag_offsets2(int lane, int wm, int wn) {
    FragOffsets2 fo;
    {
        int rl = lane & 15;
        int cb = (lane >> 4) & 1;
        #pragma unroll
        for (int mt = 0; mt < 4; mt++) {
            int r = wm * 64 + mt * 16 + rl;
            fo.a[mt] = (uint32_t)r * ROWB2 + (uint32_t)((cb ^ ((r >> 1) & 3)) << 4);
        }
    }
    {
        int g = lane >> 3;
        int cb = g & 1;
        #pragma unroll
        for (int p = 0; p < 2; p++) {
            int r = wn * 32 + (2 * p + (g >> 1)) * 8 + (lane & 7);
            fo.b[p] = (uint32_t)r * ROWB2 + (uint32_t)((cb ^ ((r >> 1) & 3)) << 4);
        }
    }
    return fo;
}

__device__ __forceinline__ void compute_ks2(uint32_t aB, uint32_t bB,
                                            const FragOffsets2& fo, float c[4][4][4],
                                            uint32_t kx) {
    uint32_t af[4][4], bq[2][4];
    #pragma unroll
    for (int mt = 0; mt < 4; mt++) ldsm_x4(af[mt], aB + (fo.a[mt] ^ kx));
    #pragma unroll
    for (int p = 0; p < 2; p++)   ldsm_x4(bq[p], bB + (fo.b[p] ^ kx));
    #pragma unroll
    for (int mt = 0; mt < 4; mt++)
        #pragma unroll
        for (int nt = 0; nt < 4; nt++)
            mma_f16(c[mt][nt], af[mt], &bq[nt >> 1][(nt & 1) * 2]);
}

__global__ void __launch_bounds__(256, 2) gemm2_h(float* __restrict__ O) {
    extern __shared__ __align__(16) uint8_t smem2[];
    uint8_t* As = smem2;                    // 4 x BUFB2
    uint8_t* Bs = smem2 + 4 * BUFB2;        // 4 x BUFB2

    const int tid  = threadIdx.x;
    const int lane = tid & 31;
    const int wid  = tid >> 5;
    const int wm   = wid >> 2, wn = wid & 3;
    const int fr = lane >> 2, fc = lane & 3;
    const int bm = blockIdx.y * 128, bn = blockIdx.x * 128;

    const int lr = tid >> 1;
    const int hh = tid & 1;
    const int swl = (lr >> 1) & 3;
    const uint32_t st0 = (uint32_t)lr * ROWB2 + (uint32_t)(((2 * hh)     ^ swl) << 4);
    const uint32_t st1 = (uint32_t)lr * ROWB2 + (uint32_t)(((2 * hh + 1) ^ swl) << 4);

    const __half* pA = g_Wh  + (size_t)(bm + lr) * PK + hh * 16;
    const __half* pB = g_Vth + (size_t)(bn + lr) * PK + hh * 16;

    float c[4][4][4];
    #pragma unroll
    for (int i = 0; i < 4; i++)
        #pragma unroll
        for (int j = 0; j < 4; j++)
            #pragma unroll
            for (int r = 0; r < 4; r++) c[i][j][r] = 0.f;

    const FragOffsets2 fo = make_frag_offsets2(lane, wm, wn);
    const uint32_t sbA = smem_u32(As);
    const uint32_t sbB = smem_u32(Bs);

    auto stage = [&](int t) {
        int buf = t & 3;
        uint32_t ab = sbA + (uint32_t)buf * BUFB2;
        uint32_t bb = sbB + (uint32_t)buf * BUFB2;
        const __half* ga = pA + t * 32;
        const __half* gb = pB + t * 32;
        CP_ASYNC16(ab + st0, (const void*)__cvta_generic_to_global(ga));
        CP_ASYNC16(ab + st1, (const void*)__cvta_generic_to_global(ga + 8));
        CP_ASYNC16(bb + st0, (const void*)__cvta_generic_to_global(gb));
        CP_ASYNC16(bb + st1, (const void*)__cvta_generic_to_global(gb + 8));
        CP_COMMIT();
    };

    stage(0); stage(1); stage(2);

    const int T = PK / 32;   // 128
    #pragma unroll 1
    for (int t = 0; t < T; t++) {
        CP_WAIT2();            // groups 0..t complete (3 prestaged + 1/iter)
        __syncthreads();
        if (t + 3 < T) stage(t + 3);   // into buf (t-1)&3: quiescent after bar(t)
        else           CP_COMMIT();    // keep group accounting exact
        int buf = t & 3;
        uint32_t aB = sbA + (uint32_t)buf * BUFB2;
        uint32_t bB = sbB + (uint32_t)buf * BUFB2;
        compute_ks2(aB, bB, fo, c, 0);
        compute_ks2(aB, bB, fo, c, 32);
    }

    #pragma unroll
    for (int mt = 0; mt < 4; mt++) {
        int row0 = bm + wm * 64 + mt * 16 + fr;
        float inv0 = g_inv_rowsum[row0];
        float inv1 = g_inv_rowsum[row0 + 8];
        #pragma unroll
        for (int nt = 0; nt < 4; nt++) {
            int col = bn + wn * 32 + nt * 8 + 2 * fc;
            if (col < CC) {
                float2 o0, o1;
                o0.x = c[mt][nt][0] * inv0; o0.y = c[mt][nt][1] * inv0;
                o1.x = c[mt][nt][2] * inv1; o1.y = c[mt][nt][3] * inv1;
                *reinterpret_cast<float2*>(&O[(size_t)row0 * CC + col])       = o0;
                *reinterpret_cast<float2*>(&O[(size_t)(row0 + 8) * CC + col]) = o1;
            }
        }
    }
}

// ---------------------------------------------------------------------------
extern "C" void kernel_launch(void* const* d_in, const int* in_sizes, int n_in,
                              void* d_out, int out_size) {
    const float* X = (const float*)d_in[0];
    const float* K = (const float*)d_in[1];
    const float* V = (const float*)d_in[2];
    float* O = (float*)d_out;
    (void)in_sizes; (void)n_in; (void)out_size;

    static bool attr_done = false;
    if (!attr_done) {
        cudaFuncSetAttribute(gemm2_h, cudaFuncAttributeMaxDynamicSharedMemorySize, SMEM2_SZ);
        attr_done = true;
    }

    row_norm2_all<<<BQ + PK, 128>>>(X, K);
    transpose_vh_kernel<<<dim3(NPAD / 32, PK / 32), dim3(32, 8)>>>(V);

    gemm1_h<<<dim3(PK / 128, BQ / 128), 256>>>(X, K);

    reduce_rowsum_kernel<<<64, 128>>>();

    gemm2_h<<<dim3((CC + 127) / 128, BQ / 128), 256, SMEM2_SZ>>>(O);
}

// round 16
// speedup vs baseline: 1.4708x; 1.4708x over previous
#include <cuda_runtime.h>
#include <cuda_fp16.h>
#include <cstdint>

#define BQ 8192
#define DD 512
#define PK 4096
#define CC 1000
#define NPAD 1024
#define EPS_F 1e-3f
#define NT1 (PK / 128)   // 32 partials per row

// ---------------- scratch ----------------
__device__ __align__(16) __half g_Wh[(size_t)BQ * PK];
__device__ __align__(16) __half g_Vth[(size_t)NPAD * PK];
__device__ float g_part[(size_t)BQ * NT1];
__device__ float g_inv_rowsum[BQ];
__device__ float g_xn2[BQ];
__device__ float g_kn2[PK];

// ---------------- helpers ----------------
__device__ __forceinline__ uint32_t smem_u32(const void* p) {
    uint32_t a;
    asm("{ .reg .u64 t; cvta.to.shared.u64 t, %1; cvt.u32.u64 %0, t; }" : "=r"(a) : "l"(p));
    return a;
}

__device__ __forceinline__ uint32_t pack_h2(float a, float b) {
    __half2 h = __floats2half2_rn(a, b);
    return *reinterpret_cast<uint32_t*>(&h);
}

__device__ __forceinline__ void mma_f16(float* c, const uint32_t* a, const uint32_t* b) {
    asm volatile(
        "mma.sync.aligned.m16n8k16.row.col.f32.f16.f16.f32 "
        "{%0,%1,%2,%3},{%4,%5,%6,%7},{%8,%9},{%0,%1,%2,%3};"
        : "+f"(c[0]), "+f"(c[1]), "+f"(c[2]), "+f"(c[3])
        : "r"(a[0]), "r"(a[1]), "r"(a[2]), "r"(a[3]), "r"(b[0]), "r"(b[1]));
}

__device__ __forceinline__ void ldsm_x4(uint32_t* r, uint32_t addr) {
    asm volatile("ldmatrix.sync.aligned.m8n8.x4.shared.b16 {%0,%1,%2,%3}, [%4];"
        : "=r"(r[0]), "=r"(r[1]), "=r"(r[2]), "=r"(r[3]) : "r"(addr));
}

#define CP_ASYNC16(dst, src) \
    asm volatile("cp.async.cg.shared.global [%0], [%1], 16;" :: "r"(dst), "l"(src) : "memory")
#define CP_COMMIT()  asm volatile("cp.async.commit_group;" ::: "memory")
#define CP_WAIT1()   asm volatile("cp.async.wait_group 1;" ::: "memory")

// GEMM1 smem: 128 rows x 32B; byte(r,c) = r*32 + ((c ^ ((r>>2)&1))<<4)
#define ROWB1  32
#define BUFB1  4096
// GEMM2 smem: 128 rows x 64B; byte(r,c) = r*64 + ((c ^ ((r>>1)&3))<<4)
#define ROWB2  64
#define BUFB2  8192

// ---------------- small kernels ----------------
// Merged norms: blocks [0, BQ) -> X rows, [BQ, BQ+PK) -> K rows
__global__ void row_norm2_all(const float* __restrict__ X, const float* __restrict__ K) {
    int b = blockIdx.x;
    const float* src;
    int row;
    if (b < BQ) { src = X + (size_t)b * DD; row = b; }
    else        { src = K + (size_t)(b - BQ) * DD; row = b - BQ; }
    float s = 0.f;
    for (int i = threadIdx.x; i < DD; i += blockDim.x) { float v = src[i]; s = fmaf(v, v, s); }
    #pragma unroll
    for (int o = 16; o > 0; o >>= 1) s += __shfl_xor_sync(0xffffffffu, s, o);
    __shared__ float red[4];
    if ((threadIdx.x & 31) == 0) red[threadIdx.x >> 5] = s;
    __syncthreads();
    if (threadIdx.x == 0) {
        float t = red[0] + red[1] + red[2] + red[3];
        if (b < BQ) g_xn2[row] = t; else g_kn2[row] = t;
    }
}

__global__ void transpose_vh_kernel(const float* __restrict__ V) {
    __shared__ float t[32][33];
    int nb = blockIdx.x * 32, kb = blockIdx.y * 32;
    int tx = threadIdx.x, ty = threadIdx.y;
    #pragma unroll
    for (int i = 0; i < 32; i += 8) {
        float v = 0.f;
        if (nb + tx < CC) v = V[(size_t)(kb + ty + i) * CC + nb + tx];
        t[ty + i][tx] = v;
    }
    __syncthreads();
    #pragma unroll
    for (int i = 0; i < 32; i += 8)
        g_Vth[(size_t)(nb + ty + i) * PK + kb + tx] = __float2half_rn(t[tx][ty + i]);
}

__global__ void reduce_rowsum_kernel() {
    int r = blockIdx.x * blockDim.x + threadIdx.x;
    if (r < BQ) {
        const float4* p = reinterpret_cast<const float4*>(&g_part[(size_t)r * NT1]);
        float s = 0.f;
        #pragma unroll
        for (int i = 0; i < NT1 / 4; i++) {
            float4 v = p[i];
            s += (v.x + v.y) + (v.z + v.w);
        }
        g_inv_rowsum[r] = 1.f / s;
    }
}

// ============================ GEMM1 (R13 verbatim) ============================
struct FragOffsets1 {
    uint32_t a[4];
    uint32_t b[2];
};

__device__ __forceinline__ FragOffsets1 make_frag_offsets1(int lane, int wm, int wn) {
    FragOffsets1 fo;
    {
        int r0 = wm * 64 + (lane & 7) + ((lane >> 3) & 1) * 8;
        int c  = (lane >> 4) & 1;
        int sw = (r0 >> 2) & 1;
        #pragma unroll
        for (int mt = 0; mt < 4; mt++)
            fo.a[mt] = (uint32_t)(r0 + mt * 16) * ROWB1 + (uint32_t)((c ^ sw) << 4);
    }
    {
        int g = lane >> 3;
        int c = g & 1;
        #pragma unroll
        for (int p = 0; p < 2; p++) {
            int r = wn * 32 + (2 * p + (g >> 1)) * 8 + (lane & 7);
            fo.b[p] = (uint32_t)r * ROWB1 + (uint32_t)((c ^ ((r >> 2) & 1)) << 4);
        }
    }
    return fo;
}

__device__ __forceinline__ void compute_tile1(uint32_t aB, uint32_t bB,
                                              const FragOffsets1& fo, float c[4][4][4]) {
    uint32_t af[4][4], bq[2][4];
    #pragma unroll
    for (int mt = 0; mt < 4; mt++) ldsm_x4(af[mt], aB + fo.a[mt]);
    #pragma unroll
    for (int p = 0; p < 2; p++)   ldsm_x4(bq[p], bB + fo.b[p]);
    #pragma unroll
    for (int mt = 0; mt < 4; mt++)
        #pragma unroll
        for (int nt = 0; nt < 4; nt++)
            mma_f16(c[mt][nt], af[mt], &bq[nt >> 1][(nt & 1) * 2]);
}

__global__ void __launch_bounds__(256) gemm1_h(const float* __restrict__ X,
                                               const float* __restrict__ Km) {
    __shared__ __align__(16) uint8_t As[2][BUFB1];
    __shared__ __align__(16) uint8_t Bs[2][BUFB1];
    __shared__ float rs[128 * 4];

    const int tid  = threadIdx.x;
    const int lane = tid & 31;
    const int wid  = tid >> 5;
    const int wm   = wid >> 2, wn = wid & 3;
    const int fr = lane >> 2, fc = lane & 3;
    const int bm = blockIdx.y * 128, bn = blockIdx.x * 128;

    const int lm  = tid >> 2;
    const int lk4 = (tid & 3) * 4;
    const int ch  = (tid & 3) >> 1;
    const int h8  = tid & 1;
    const int sw  = (lm >> 2) & 1;
    const uint32_t soA0 = (uint32_t)lm * ROWB1        + (uint32_t)((ch ^ sw) << 4) + h8 * 8;
    const uint32_t soA1 = (uint32_t)(lm + 64) * ROWB1 + (uint32_t)((ch ^ sw) << 4) + h8 * 8;

    const float* pA0 = X  + (size_t)(bm + lm) * DD + lk4;
    const float* pA1 = pA0 + (size_t)64 * DD;
    const float* pB0 = Km + (size_t)(bn + lm) * DD + lk4;
    const float* pB1 = pB0 + (size_t)64 * DD;

    float4 ra0 = *reinterpret_cast<const float4*>(pA0);
    float4 ra1 = *reinterpret_cast<const float4*>(pA1);
    float4 rb0 = *reinterpret_cast<const float4*>(pB0);
    float4 rb1 = *reinterpret_cast<const float4*>(pB1);

    float c[4][4][4];
    #pragma unroll
    for (int i = 0; i < 4; i++)
        #pragma unroll
        for (int j = 0; j < 4; j++)
            #pragma unroll
            for (int r = 0; r < 4; r++) c[i][j][r] = 0.f;

    const FragOffsets1 fo = make_frag_offsets1(lane, wm, wn);
    const uint32_t sbA = smem_u32(&As[0][0]);
    const uint32_t sbB = smem_u32(&Bs[0][0]);

    const int T = DD / 16;      // 32
    #pragma unroll 1
    for (int t = 0; t < T; t++) {
        int buf = t & 1;
        {
            uint2 u;
            u.x = pack_h2(ra0.x, ra0.y); u.y = pack_h2(ra0.z, ra0.w);
            *reinterpret_cast<uint2*>(&As[buf][soA0]) = u;
            u.x = pack_h2(ra1.x, ra1.y); u.y = pack_h2(ra1.z, ra1.w);
            *reinterpret_cast<uint2*>(&As[buf][soA1]) = u;
            u.x = pack_h2(rb0.x, rb0.y); u.y = pack_h2(rb0.z, rb0.w);
            *reinterpret_cast<uint2*>(&Bs[buf][soA0]) = u;
            u.x = pack_h2(rb1.x, rb1.y); u.y = pack_h2(rb1.z, rb1.w);
            *reinterpret_cast<uint2*>(&Bs[buf][soA1]) = u;
        }
        __syncthreads();
        if (t + 1 < T) {
            int off = (t + 1) * 16;
            ra0 = *reinterpret_cast<const float4*>(pA0 + off);
            ra1 = *reinterpret_cast<const float4*>(pA1 + off);
            rb0 = *reinterpret_cast<const float4*>(pB0 + off);
            rb1 = *reinterpret_cast<const float4*>(pB1 + off);
        }
        compute_tile1(sbA + buf * BUFB1, sbB + buf * BUFB1, fo, c);
    }

    // Epilogue: W -> g_Wh (half) + fused row-sum partials
    float rsum[4][2];
    #pragma unroll
    for (int mt = 0; mt < 4; mt++) { rsum[mt][0] = 0.f; rsum[mt][1] = 0.f; }

    #pragma unroll
    for (int mt = 0; mt < 4; mt++) {
        int row0 = bm + wm * 64 + mt * 16 + fr;
        float xn0 = g_xn2[row0];
        float xn1 = g_xn2[row0 + 8];
        #pragma unroll
        for (int nt = 0; nt < 4; nt++) {
            int col = bn + wn * 32 + nt * 8 + 2 * fc;
            float kn0 = g_kn2[col], kn1 = g_kn2[col + 1];
            float w00 = 1.f / (EPS_F + fmaxf(fmaf(-2.f, c[mt][nt][0], xn0 + kn0), 0.f));
            float w01 = 1.f / (EPS_F + fmaxf(fmaf(-2.f, c[mt][nt][1], xn0 + kn1), 0.f));
            float w10 = 1.f / (EPS_F + fmaxf(fmaf(-2.f, c[mt][nt][2], xn1 + kn0), 0.f));
            float w11 = 1.f / (EPS_F + fmaxf(fmaf(-2.f, c[mt][nt][3], xn1 + kn1), 0.f));
            __half2 h0 = __floats2half2_rn(w00, w01);
            __half2 h1 = __floats2half2_rn(w10, w11);
            float2 f0 = __half22float2(h0), f1 = __half22float2(h1);
            rsum[mt][0] += f0.x + f0.y;
            rsum[mt][1] += f1.x + f1.y;
            *reinterpret_cast<__half2*>(&g_Wh[(size_t)row0 * PK + col])       = h0;
            *reinterpret_cast<__half2*>(&g_Wh[(size_t)(row0 + 8) * PK + col]) = h1;
        }
    }

    __syncthreads();
    #pragma unroll
    for (int mt = 0; mt < 4; mt++) {
        #pragma unroll
        for (int rh = 0; rh < 2; rh++) {
            float v = rsum[mt][rh];
            v += __shfl_xor_sync(0xffffffffu, v, 1);
            v += __shfl_xor_sync(0xffffffffu, v, 2);
            if (fc == 0) {
                int rl = wm * 64 + mt * 16 + fr + rh * 8;
                rs[rl * 4 + wn] = v;
            }
        }
    }
    __syncthreads();
    if (tid < 128) {
        float s = rs[tid * 4] + rs[tid * 4 + 1] + rs[tid * 4 + 2] + rs[tid * 4 + 3];
        g_part[(size_t)(bm + tid) * NT1 + blockIdx.x] = s;
    }
}

// ============================ GEMM2 (R13 verbatim: cp.async 3-stage ring, 48KB static) ============================
struct FragOffsets2 {
    uint32_t a[4];
    uint32_t b[2];
};

__device__ __forceinline__ FragOffsets2 make_frag_offsets2(int lane, int wm, int wn) {
    FragOffsets2 fo;
    {
        int rl = lane & 15;
        int cb = (lane >> 4) & 1;
        #pragma unroll
        for (int mt = 0; mt < 4; mt++) {
            int r = wm * 64 + mt * 16 + rl;
            fo.a[mt] = (uint32_t)r * ROWB2 + (uint32_t)((cb ^ ((r >> 1) & 3)) << 4);
        }
    }
    {
        int g = lane >> 3;
        int cb = g & 1;
        #pragma unroll
        for (int p = 0; p < 2; p++) {
            int r = wn * 32 + (2 * p + (g >> 1)) * 8 + (lane & 7);
            fo.b[p] = (uint32_t)r * ROWB2 + (uint32_t)((cb ^ ((r >> 1) & 3)) << 4);
        }
    }
    return fo;
}

__device__ __forceinline__ void compute_ks2(uint32_t aB, uint32_t bB,
                                            const FragOffsets2& fo, float c[4][4][4],
                                            uint32_t kx) {
    uint32_t af[4][4], bq[2][4];
    #pragma unroll
    for (int mt = 0; mt < 4; mt++) ldsm_x4(af[mt], aB + (fo.a[mt] ^ kx));
    #pragma unroll
    for (int p = 0; p < 2; p++)   ldsm_x4(bq[p], bB + (fo.b[p] ^ kx));
    #pragma unroll
    for (int mt = 0; mt < 4; mt++)
        #pragma unroll
        for (int nt = 0; nt < 4; nt++)
            mma_f16(c[mt][nt], af[mt], &bq[nt >> 1][(nt & 1) * 2]);
}

__global__ void __launch_bounds__(256) gemm2_h(float* __restrict__ O) {
    __shared__ __align__(16) uint8_t As[3][BUFB2];
    __shared__ __align__(16) uint8_t Bs[3][BUFB2];

    const int tid  = threadIdx.x;
    const int lane = tid & 31;
    const int wid  = tid >> 5;
    const int wm   = wid >> 2, wn = wid & 3;
    const int fr = lane >> 2, fc = lane & 3;
    const int bm = blockIdx.y * 128, bn = blockIdx.x * 128;

    const int lr = tid >> 1;
    const int hh = tid & 1;
    const int swl = (lr >> 1) & 3;
    const uint32_t st0 = (uint32_t)lr * ROWB2 + (uint32_t)(((2 * hh)     ^ swl) << 4);
    const uint32_t st1 = (uint32_t)lr * ROWB2 + (uint32_t)(((2 * hh + 1) ^ swl) << 4);

    const __half* pA = g_Wh  + (size_t)(bm + lr) * PK + hh * 16;
    const __half* pB = g_Vth + (size_t)(bn + lr) * PK + hh * 16;

    float c[4][4][4];
    #pragma unroll
    for (int i = 0; i < 4; i++)
        #pragma unroll
        for (int j = 0; j < 4; j++)
            #pragma unroll
            for (int r = 0; r < 4; r++) c[i][j][r] = 0.f;

    const FragOffsets2 fo = make_frag_offsets2(lane, wm, wn);
    const uint32_t sbA = smem_u32(&As[0][0]);
    const uint32_t sbB = smem_u32(&Bs[0][0]);

    auto stage = [&](int t, int buf) {
        uint32_t ab = sbA + (uint32_t)buf * BUFB2;
        uint32_t bb = sbB + (uint32_t)buf * BUFB2;
        const __half* ga = pA + t * 32;
        const __half* gb = pB + t * 32;
        CP_ASYNC16(ab + st0, (const void*)__cvta_generic_to_global(ga));
        CP_ASYNC16(ab + st1, (const void*)__cvta_generic_to_global(ga + 8));
        CP_ASYNC16(bb + st0, (const void*)__cvta_generic_to_global(gb));
        CP_ASYNC16(bb + st1, (const void*)__cvta_generic_to_global(gb + 8));
        CP_COMMIT();
    };

    stage(0, 0);
    stage(1, 1);

    const int T = PK / 32;   // 128
    int cbuf = 0, sbuf = 2;
    #pragma unroll 1
    for (int t = 0; t < T; t++) {
        CP_WAIT1();
        __syncthreads();
        if (t + 2 < T) stage(t + 2, sbuf);
        else           CP_COMMIT();
        uint32_t aB = sbA + (uint32_t)cbuf * BUFB2;
        uint32_t bB = sbB + (uint32_t)cbuf * BUFB2;
        compute_ks2(aB, bB, fo, c, 0);
        compute_ks2(aB, bB, fo, c, 32);
        cbuf = (cbuf == 2) ? 0 : cbuf + 1;
        sbuf = (sbuf == 2) ? 0 : sbuf + 1;
    }

    #pragma unroll
    for (int mt = 0; mt < 4; mt++) {
        int row0 = bm + wm * 64 + mt * 16 + fr;
        float inv0 = g_inv_rowsum[row0];
        float inv1 = g_inv_rowsum[row0 + 8];
        #pragma unroll
        for (int nt = 0; nt < 4; nt++) {
            int col = bn + wn * 32 + nt * 8 + 2 * fc;
            if (col < CC) {
                float2 o0, o1;
                o0.x = c[mt][nt][0] * inv0; o0.y = c[mt][nt][1] * inv0;
                o1.x = c[mt][nt][2] * inv1; o1.y = c[mt][nt][3] * inv1;
                *reinterpret_cast<float2*>(&O[(size_t)row0 * CC + col])       = o0;
                *reinterpret_cast<float2*>(&O[(size_t)(row0 + 8) * CC + col]) = o1;
            }
        }
    }
}

// ---------------------------------------------------------------------------
extern "C" void kernel_launch(void* const* d_in, const int* in_sizes, int n_in,
                              void* d_out, int out_size) {
    const float* X = (const float*)d_in[0];
    const float* K = (const float*)d_in[1];
    const float* V = (const float*)d_in[2];
    float* O = (float*)d_out;
    (void)in_sizes; (void)n_in; (void)out_size;

    row_norm2_all<<<BQ + PK, 128>>>(X, K);
    transpose_vh_kernel<<<dim3(NPAD / 32, PK / 32), dim3(32, 8)>>>(V);

    gemm1_h<<<dim3(PK / 128, BQ / 128), 256>>>(X, K);

    reduce_rowsum_kernel<<<64, 128>>>();

    gemm2_h<<<dim3((CC + 127) / 128, BQ / 128), 256>>>(O);
}

// round 17
// speedup vs baseline: 1.5741x; 1.0703x over previous
#include <cuda_runtime.h>
#include <cuda_fp16.h>
#include <cstdint>

#define BQ 8192
#define DD 512
#define PK 4096
#define CC 1000
#define NPAD 1024
#define EPS_F 1e-3f
#define NT1 (PK / 128)   // 32 partials per row

// ---------------- scratch (device code access ONLY — never passed from host) ----------------
__device__ __align__(16) __half g_Xh[(size_t)BQ * DD];
__device__ __align__(16) __half g_Kh[(size_t)PK * DD];
__device__ __align__(16) __half g_Wh[(size_t)BQ * PK];
__device__ __align__(16) __half g_Vth[(size_t)NPAD * PK];
__device__ float g_part[(size_t)BQ * NT1];
__device__ float g_inv_rowsum[BQ];
__device__ float g_xn2[BQ];
__device__ float g_kn2[PK];

// ---------------- helpers ----------------
__device__ __forceinline__ uint32_t smem_u32(const void* p) {
    uint32_t a;
    asm("{ .reg .u64 t; cvta.to.shared.u64 t, %1; cvt.u32.u64 %0, t; }" : "=r"(a) : "l"(p));
    return a;
}

__device__ __forceinline__ uint32_t pack_h2(float a, float b) {
    __half2 h = __floats2half2_rn(a, b);
    return *reinterpret_cast<uint32_t*>(&h);
}

__device__ __forceinline__ void mma_f16(float* c, const uint32_t* a, const uint32_t* b) {
    asm volatile(
        "mma.sync.aligned.m16n8k16.row.col.f32.f16.f16.f32 "
        "{%0,%1,%2,%3},{%4,%5,%6,%7},{%8,%9},{%0,%1,%2,%3};"
        : "+f"(c[0]), "+f"(c[1]), "+f"(c[2]), "+f"(c[3])
        : "r"(a[0]), "r"(a[1]), "r"(a[2]), "r"(a[3]), "r"(b[0]), "r"(b[1]));
}

__device__ __forceinline__ void ldsm_x4(uint32_t* r, uint32_t addr) {
    asm volatile("ldmatrix.sync.aligned.m8n8.x4.shared.b16 {%0,%1,%2,%3}, [%4];"
        : "=r"(r[0]), "=r"(r[1]), "=r"(r[2]), "=r"(r[3]) : "r"(addr));
}

#define CP_ASYNC16(dst, src) \
    asm volatile("cp.async.cg.shared.global [%0], [%1], 16;" :: "r"(dst), "l"(src) : "memory")
#define CP_COMMIT()  asm volatile("cp.async.commit_group;" ::: "memory")
#define CP_WAIT1()   asm volatile("cp.async.wait_group 1;" ::: "memory")

// GEMM smem: 128 rows x 64B (k-tile 32); byte(r,c) = r*64 + ((c ^ ((r>>1)&3))<<4)
#define ROWB2  64
#define BUFB2  8192

// ---------------- small kernels ----------------
// Merged norms + half conversion. Outputs written via device-symbol refs ONLY.
__global__ void norm_cvt_all(const float* __restrict__ X, const float* __restrict__ K) {
    int b = blockIdx.x;
    const float* src;
    __half* dst;
    int row;
    if (b < BQ) { row = b;      src = X + (size_t)row * DD; dst = g_Xh + (size_t)row * DD; }
    else        { row = b - BQ; src = K + (size_t)row * DD; dst = g_Kh + (size_t)row * DD; }
    int i4 = threadIdx.x * 4;
    float4 v = *reinterpret_cast<const float4*>(src + i4);
    float s = fmaf(v.x, v.x, fmaf(v.y, v.y, fmaf(v.z, v.z, v.w * v.w)));
    uint2 u;
    u.x = pack_h2(v.x, v.y);
    u.y = pack_h2(v.z, v.w);
    *reinterpret_cast<uint2*>(dst + i4) = u;
    #pragma unroll
    for (int o = 16; o > 0; o >>= 1) s += __shfl_xor_sync(0xffffffffu, s, o);
    __shared__ float red[4];
    if ((threadIdx.x & 31) == 0) red[threadIdx.x >> 5] = s;
    __syncthreads();
    if (threadIdx.x == 0) {
        float t = red[0] + red[1] + red[2] + red[3];
        if (b < BQ) g_xn2[row] = t; else g_kn2[row] = t;
    }
}

__global__ void transpose_vh_kernel(const float* __restrict__ V) {
    __shared__ float t[32][33];
    int nb = blockIdx.x * 32, kb = blockIdx.y * 32;
    int tx = threadIdx.x, ty = threadIdx.y;
    #pragma unroll
    for (int i = 0; i < 32; i += 8) {
        float v = 0.f;
        if (nb + tx < CC) v = V[(size_t)(kb + ty + i) * CC + nb + tx];
        t[ty + i][tx] = v;
    }
    __syncthreads();
    #pragma unroll
    for (int i = 0; i < 32; i += 8)
        g_Vth[(size_t)(nb + ty + i) * PK + kb + tx] = __float2half_rn(t[tx][ty + i]);
}

__global__ void reduce_rowsum_kernel() {
    int r = blockIdx.x * blockDim.x + threadIdx.x;
    if (r < BQ) {
        const float4* p = reinterpret_cast<const float4*>(&g_part[(size_t)r * NT1]);
        float s = 0.f;
        #pragma unroll
        for (int i = 0; i < NT1 / 4; i++) {
            float4 v = p[i];
            s += (v.x + v.y) + (v.z + v.w);
        }
        g_inv_rowsum[r] = 1.f / s;
    }
}

// ---------------- shared fragment machinery (k32 layout, proven) ----------------
struct FragOffsets {
    uint32_t a[4];
    uint32_t b[2];
};

__device__ __forceinline__ FragOffsets make_frag_offsets(int lane, int wm, int wn) {
    FragOffsets fo;
    {
        int rl = lane & 15;
        int cb = (lane >> 4) & 1;
        #pragma unroll
        for (int mt = 0; mt < 4; mt++) {
            int r = wm * 64 + mt * 16 + rl;
            fo.a[mt] = (uint32_t)r * ROWB2 + (uint32_t)((cb ^ ((r >> 1) & 3)) << 4);
        }
    }
    {
        int g = lane >> 3;
        int cb = g & 1;
        #pragma unroll
        for (int p = 0; p < 2; p++) {
            int r = wn * 32 + (2 * p + (g >> 1)) * 8 + (lane & 7);
            fo.b[p] = (uint32_t)r * ROWB2 + (uint32_t)((cb ^ ((r >> 1) & 3)) << 4);
        }
    }
    return fo;
}

__device__ __forceinline__ void compute_ks(uint32_t aB, uint32_t bB,
                                           const FragOffsets& fo, float c[4][4][4],
                                           uint32_t kx) {
    uint32_t af[4][4], bq[2][4];
    #pragma unroll
    for (int mt = 0; mt < 4; mt++) ldsm_x4(af[mt], aB + (fo.a[mt] ^ kx));
    #pragma unroll
    for (int p = 0; p < 2; p++)   ldsm_x4(bq[p], bB + (fo.b[p] ^ kx));
    #pragma unroll
    for (int mt = 0; mt < 4; mt++)
        #pragma unroll
        for (int nt = 0; nt < 4; nt++)
            mma_f16(c[mt][nt], af[mt], &bq[nt >> 1][(nt & 1) * 2]);
}

// ============================ GEMM1 (gemm2's proven ring, half X/K sources) ============================
__global__ void __launch_bounds__(256) gemm1_h() {
    __shared__ __align__(16) uint8_t As[3][BUFB2];
    __shared__ __align__(16) uint8_t Bs[3][BUFB2];

    const int tid  = threadIdx.x;
    const int lane = tid & 31;
    const int wid  = tid >> 5;
    const int wm   = wid >> 2, wn = wid & 3;
    const int fr = lane >> 2, fc = lane & 3;
    const int bm = blockIdx.y * 128, bn = blockIdx.x * 128;

    const int lr = tid >> 1;
    const int hh = tid & 1;
    const int swl = (lr >> 1) & 3;
    const uint32_t st0 = (uint32_t)lr * ROWB2 + (uint32_t)(((2 * hh)     ^ swl) << 4);
    const uint32_t st1 = (uint32_t)lr * ROWB2 + (uint32_t)(((2 * hh + 1) ^ swl) << 4);

    const __half* pA = g_Xh + (size_t)(bm + lr) * DD + hh * 16;
    const __half* pB = g_Kh + (size_t)(bn + lr) * DD + hh * 16;

    float c[4][4][4];
    #pragma unroll
    for (int i = 0; i < 4; i++)
        #pragma unroll
        for (int j = 0; j < 4; j++)
            #pragma unroll
            for (int r = 0; r < 4; r++) c[i][j][r] = 0.f;

    const FragOffsets fo = make_frag_offsets(lane, wm, wn);
    const uint32_t sbA = smem_u32(&As[0][0]);
    const uint32_t sbB = smem_u32(&Bs[0][0]);

    auto stage = [&](int t, int buf) {
        uint32_t ab = sbA + (uint32_t)buf * BUFB2;
        uint32_t bb = sbB + (uint32_t)buf * BUFB2;
        const __half* ga = pA + t * 32;
        const __half* gb = pB + t * 32;
        CP_ASYNC16(ab + st0, (const void*)__cvta_generic_to_global(ga));
        CP_ASYNC16(ab + st1, (const void*)__cvta_generic_to_global(ga + 8));
        CP_ASYNC16(bb + st0, (const void*)__cvta_generic_to_global(gb));
        CP_ASYNC16(bb + st1, (const void*)__cvta_generic_to_global(gb + 8));
        CP_COMMIT();
    };

    stage(0, 0);
    stage(1, 1);

    const int T = DD / 32;   // 16
    int cbuf = 0, sbuf = 2;
    #pragma unroll 1
    for (int t = 0; t < T; t++) {
        CP_WAIT1();
        __syncthreads();
        if (t + 2 < T) stage(t + 2, sbuf);
        else           CP_COMMIT();
        uint32_t aB = sbA + (uint32_t)cbuf * BUFB2;
        uint32_t bB = sbB + (uint32_t)cbuf * BUFB2;
        compute_ks(aB, bB, fo, c, 0);
        compute_ks(aB, bB, fo, c, 32);
        cbuf = (cbuf == 2) ? 0 : cbuf + 1;
        sbuf = (sbuf == 2) ? 0 : sbuf + 1;
    }

    // Epilogue: W -> g_Wh (half) + fused row-sum partials (R13 verbatim; rs aliases As)
    float rsum[4][2];
    #pragma unroll
    for (int mt = 0; mt < 4; mt++) { rsum[mt][0] = 0.f; rsum[mt][1] = 0.f; }

    #pragma unroll
    for (int mt = 0; mt < 4; mt++) {
        int row0 = bm + wm * 64 + mt * 16 + fr;
        float xn0 = g_xn2[row0];
        float xn1 = g_xn2[row0 + 8];
        #pragma unroll
        for (int nt = 0; nt < 4; nt++) {
            int col = bn + wn * 32 + nt * 8 + 2 * fc;
            float kn0 = g_kn2[col], kn1 = g_kn2[col + 1];
            float w00 = 1.f / (EPS_F + fmaxf(fmaf(-2.f, c[mt][nt][0], xn0 + kn0), 0.f));
            float w01 = 1.f / (EPS_F + fmaxf(fmaf(-2.f, c[mt][nt][1], xn0 + kn1), 0.f));
            float w10 = 1.f / (EPS_F + fmaxf(fmaf(-2.f, c[mt][nt][2], xn1 + kn0), 0.f));
            float w11 = 1.f / (EPS_F + fmaxf(fmaf(-2.f, c[mt][nt][3], xn1 + kn1), 0.f));
            __half2 h0 = __floats2half2_rn(w00, w01);
            __half2 h1 = __floats2half2_rn(w10, w11);
            float2 f0 = __half22float2(h0), f1 = __half22float2(h1);
            rsum[mt][0] += f0.x + f0.y;
            rsum[mt][1] += f1.x + f1.y;
            *reinterpret_cast<__half2*>(&g_Wh[(size_t)row0 * PK + col])       = h0;
            *reinterpret_cast<__half2*>(&g_Wh[(size_t)(row0 + 8) * PK + col]) = h1;
        }
    }

    float* rs = reinterpret_cast<float*>(&As[0][0]);   // mainloop smem reuse (quiescent)
    __syncthreads();
    #pragma unroll
    for (int mt = 0; mt < 4; mt++) {
        #pragma unroll
        for (int rh = 0; rh < 2; rh++) {
            float v = rsum[mt][rh];
            v += __shfl_xor_sync(0xffffffffu, v, 1);
            v += __shfl_xor_sync(0xffffffffu, v, 2);
            if (fc == 0) {
                int rl = wm * 64 + mt * 16 + fr + rh * 8;
                rs[rl * 4 + wn] = v;
            }
        }
    }
    __syncthreads();
    if (tid < 128) {
        float s = rs[tid * 4] + rs[tid * 4 + 1] + rs[tid * 4 + 2] + rs[tid * 4 + 3];
        g_part[(size_t)(bm + tid) * NT1 + blockIdx.x] = s;
    }
}

// ============================ GEMM2 (R13/R16 verbatim: cp.async 3-stage ring) ============================
__global__ void __launch_bounds__(256) gemm2_h(float* __restrict__ O) {
    __shared__ __align__(16) uint8_t As[3][BUFB2];
    __shared__ __align__(16) uint8_t Bs[3][BUFB2];

    const int tid  = threadIdx.x;
    const int lane = tid & 31;
    const int wid  = tid >> 5;
    const int wm   = wid >> 2, wn = wid & 3;
    const int fr = lane >> 2, fc = lane & 3;
    const int bm = blockIdx.y * 128, bn = blockIdx.x * 128;

    const int lr = tid >> 1;
    const int hh = tid & 1;
    const int swl = (lr >> 1) & 3;
    const uint32_t st0 = (uint32_t)lr * ROWB2 + (uint32_t)(((2 * hh)     ^ swl) << 4);
    const uint32_t st1 = (uint32_t)lr * ROWB2 + (uint32_t)(((2 * hh + 1) ^ swl) << 4);

    const __half* pA = g_Wh  + (size_t)(bm + lr) * PK + hh * 16;
    const __half* pB = g_Vth + (size_t)(bn + lr) * PK + hh * 16;

    float c[4][4][4];
    #pragma unroll
    for (int i = 0; i < 4; i++)
        #pragma unroll
        for (int j = 0; j < 4; j++)
            #pragma unroll
            for (int r = 0; r < 4; r++) c[i][j][r] = 0.f;

    const FragOffsets fo = make_frag_offsets(lane, wm, wn);
    const uint32_t sbA = smem_u32(&As[0][0]);
    const uint32_t sbB = smem_u32(&Bs[0][0]);

    auto stage = [&](int t, int buf) {
        uint32_t ab = sbA + (uint32_t)buf * BUFB2;
        uint32_t bb = sbB + (uint32_t)buf * BUFB2;
        const __half* ga = pA + t * 32;
        const __half* gb = pB + t * 32;
        CP_ASYNC16(ab + st0, (const void*)__cvta_generic_to_global(ga));
        CP_ASYNC16(ab + st1, (const void*)__cvta_generic_to_global(ga + 8));
        CP_ASYNC16(bb + st0, (const void*)__cvta_generic_to_global(gb));
        CP_ASYNC16(bb + st1, (const void*)__cvta_generic_to_global(gb + 8));
        CP_COMMIT();
    };

    stage(0, 0);
    stage(1, 1);

    const int T = PK / 32;   // 128
    int cbuf = 0, sbuf = 2;
    #pragma unroll 1
    for (int t = 0; t < T; t++) {
        CP_WAIT1();
        __syncthreads();
        if (t + 2 < T) stage(t + 2, sbuf);
        else           CP_COMMIT();
        uint32_t aB = sbA + (uint32_t)cbuf * BUFB2;
        uint32_t bB = sbB + (uint32_t)cbuf * BUFB2;
        compute_ks(aB, bB, fo, c, 0);
        compute_ks(aB, bB, fo, c, 32);
        cbuf = (cbuf == 2) ? 0 : cbuf + 1;
        sbuf = (sbuf == 2) ? 0 : sbuf + 1;
    }

    #pragma unroll
    for (int mt = 0; mt < 4; mt++) {
        int row0 = bm + wm * 64 + mt * 16 + fr;
        float inv0 = g_inv_rowsum[row0];
        float inv1 = g_inv_rowsum[row0 + 8];
        #pragma unroll
        for (int nt = 0; nt < 4; nt++) {
            int col = bn + wn * 32 + nt * 8 + 2 * fc;
            if (col < CC) {
                float2 o0, o1;
                o0.x = c[mt][nt][0] * inv0; o0.y = c[mt][nt][1] * inv0;
                o1.x = c[mt][nt][2] * inv1; o1.y = c[mt][nt][3] * inv1;
                *reinterpret_cast<float2*>(&O[(size_t)row0 * CC + col])       = o0;
                *reinterpret_cast<float2*>(&O[(size_t)(row0 + 8) * CC + col]) = o1;
            }
        }
    }
}

// ---------------------------------------------------------------------------
extern "C" void kernel_launch(void* const* d_in, const int* in_sizes, int n_in,
                              void* d_out, int out_size) {
    const float* X = (const float*)d_in[0];
    const float* K = (const float*)d_in[1];
    const float* V = (const float*)d_in[2];
    float* O = (float*)d_out;
    (void)in_sizes; (void)n_in; (void)out_size;

    norm_cvt_all<<<BQ + PK, 128>>>(X, K);
    transpose_vh_kernel<<<dim3(NPAD / 32, PK / 32), dim3(32, 8)>>>(V);

    gemm1_h<<<dim3(PK / 128, BQ / 128), 256>>>();

    reduce_rowsum_kernel<<<64, 128>>>();

    gemm2_h<<<dim3((CC + 127) / 128, BQ / 128), 256>>>(O);
}